// round 3
// baseline (speedup 1.0000x reference)
#include <cuda_runtime.h>
#include <math.h>

// Problem constants
#define BB   8
#define CC_  256
#define HH   96
#define WW   128
#define RR   4
#define DD   9                 // 2R+1
#define HWSZ (HH*WW)           // 12288
#define CHW  (CC_*HWSZ)        // 3145728

// Correlation kernel tiling
#define YT   4
#define XT   64
#define KC   8                 // channels staged per smem chunk
#define FQH  (YT + 2*RR)       // 12
#define FQW  (XT + 2*RR)       // 72
#define NTHR 576               // 16 xg * 4 yr * 9 dy

// Scratch: per-pixel inverse norms (allocation-free __device__ globals)
__device__ float g_invr[BB*HWSZ];
__device__ float g_invq[BB*HWSZ];

// ---------------------------------------------------------------------------
// Kernel 1: per-pixel inverse L2 norms of fr and fq (channel reduction)
// ---------------------------------------------------------------------------
__global__ __launch_bounds__(256) void norm_kernel(const float* __restrict__ fr,
                                                   const float* __restrict__ fq)
{
    int p = blockIdx.x * 256 + threadIdx.x;
    if (p >= BB*HWSZ) return;
    int b  = p / HWSZ;
    int yx = p - b * HWSZ;
    const float* pr = fr + (size_t)b * CHW + yx;
    const float* pq = fq + (size_t)b * CHW + yx;
    float sr = 0.f, sq = 0.f;
#pragma unroll 8
    for (int c = 0; c < CC_; c++) {
        float a = pr[(size_t)c * HWSZ];
        float d = pq[(size_t)c * HWSZ];
        sr = fmaf(a, a, sr);
        sq = fmaf(d, d, sq);
    }
    g_invr[p] = 1.f / fmaxf(sqrtf(sr), 1e-12f);
    g_invq[p] = 1.f / fmaxf(sqrtf(sq), 1e-12f);
}

// ---------------------------------------------------------------------------
// Kernel 2: banded correlation on raw tensors, scaled by inverse norms.
// Block tile: YT x XT fr pixels, ALL 81 displacements (dy split across warps,
// dx + 4 x-pixels register-tiled per thread -> 36 accumulators).
// ---------------------------------------------------------------------------
__global__ __launch_bounds__(NTHR, 1) void corr_kernel(const float* __restrict__ fr,
                                                       const float* __restrict__ fq,
                                                       float* __restrict__ out)
{
    __shared__ float s_fr[KC][YT][XT];       // 8 KB
    __shared__ float s_fq[KC][FQH][FQW];     // 27 KB
    __shared__ float s_invq[FQH][FQW];       // 3.4 KB

    const int tid = threadIdx.x;
    const int xg  = tid & 15;          // 0..15  -> x0 + xg*4
    const int yr  = (tid >> 4) & 3;    // 0..3
    const int dy  = tid / 64;          // 0..8

    const int x0 = blockIdx.x * XT;
    const int y0 = blockIdx.y * YT;
    const int b  = blockIdx.z;

    // Stage invq halo tile once (zero outside image, matching zero padding).
    for (int e = tid; e < FQH * FQW; e += NTHR) {
        int ry = e / FQW;
        int j  = e - ry * FQW;
        int gy = y0 + ry - RR;
        int gx = x0 + j  - RR;
        float v = 0.f;
        if ((unsigned)gy < (unsigned)HH && (unsigned)gx < (unsigned)WW)
            v = g_invq[b * HWSZ + gy * WW + gx];
        s_invq[ry][j] = v;
    }

    float acc[DD][4];
#pragma unroll
    for (int d = 0; d < DD; d++)
#pragma unroll
        for (int i = 0; i < 4; i++) acc[d][i] = 0.f;

    const float* frb = fr + (size_t)b * CHW;
    const float* fqb = fq + (size_t)b * CHW;

    for (int c0 = 0; c0 < CC_; c0 += KC) {
        __syncthreads();

        // ---- stage fr chunk: KC*YT*XT floats = 512 float4 loads
        if (tid < 512) {
            int cc  = tid >> 6;          // 0..7
            int rem = tid & 63;
            int yy  = rem >> 4;          // 0..3
            int xq  = rem & 15;          // 0..15
            const float4 v = *reinterpret_cast<const float4*>(
                frb + (size_t)(c0 + cc) * HWSZ + (y0 + yy) * WW + x0 + xq * 4);
            *reinterpret_cast<float4*>(&s_fr[cc][yy][xq * 4]) = v;
        }

        // ---- stage fq chunk with zero-padded halo: KC*FQH*FQW = 6912 = 12*NTHR
#pragma unroll
        for (int k = 0; k < (KC * FQH * FQW) / NTHR; k++) {
            int e   = tid + k * NTHR;
            int cc  = e / (FQH * FQW);
            int rem = e - cc * (FQH * FQW);
            int ry  = rem / FQW;
            int j   = rem - ry * FQW;
            int gy  = y0 + ry - RR;
            int gx  = x0 + j  - RR;
            float v = 0.f;
            if ((unsigned)gy < (unsigned)HH && (unsigned)gx < (unsigned)WW)
                v = fqb[(size_t)(c0 + cc) * HWSZ + gy * WW + gx];
            s_fq[cc][ry][j] = v;
        }

        __syncthreads();

        // ---- compute: per channel, 4 LDS.128 feed 36 FFMA
#pragma unroll
        for (int cc = 0; cc < KC; cc++) {
            float4 a4 = *reinterpret_cast<const float4*>(&s_fr[cc][yr][xg * 4]);
            float a[4] = {a4.x, a4.y, a4.z, a4.w};

            float q[12];
            {
                const float* qp = &s_fq[cc][yr + dy][xg * 4];
                float4 q0 = *reinterpret_cast<const float4*>(qp + 0);
                float4 q1 = *reinterpret_cast<const float4*>(qp + 4);
                float4 q2 = *reinterpret_cast<const float4*>(qp + 8);
                q[0]=q0.x; q[1]=q0.y; q[2]=q0.z; q[3]=q0.w;
                q[4]=q1.x; q[5]=q1.y; q[6]=q1.z; q[7]=q1.w;
                q[8]=q2.x; q[9]=q2.y; q[10]=q2.z; q[11]=q2.w;
            }

#pragma unroll
            for (int dx = 0; dx < DD; dx++)
#pragma unroll
                for (int i = 0; i < 4; i++)
                    acc[dx][i] = fmaf(a[i], q[i + dx], acc[dx][i]);
        }
    }

    // ---- epilogue: scale by invr * invq / 256 and store
    const int gy = y0 + yr;
    float ir[4];
#pragma unroll
    for (int i = 0; i < 4; i++)
        ir[i] = g_invr[b * HWSZ + gy * WW + x0 + xg * 4 + i] * (1.0f / 256.0f);

#pragma unroll
    for (int dx = 0; dx < DD; dx++) {
        float4 o;
        o.x = acc[dx][0] * ir[0] * s_invq[yr + dy][xg * 4 + 0 + dx];
        o.y = acc[dx][1] * ir[1] * s_invq[yr + dy][xg * 4 + 1 + dx];
        o.z = acc[dx][2] * ir[2] * s_invq[yr + dy][xg * 4 + 2 + dx];
        o.w = acc[dx][3] * ir[3] * s_invq[yr + dy][xg * 4 + 3 + dx];
        float* op = out + ((size_t)(b * (DD * DD) + dy * DD + dx) * HH + gy) * WW
                        + x0 + xg * 4;
        *reinterpret_cast<float4*>(op) = o;
    }
}

// ---------------------------------------------------------------------------
extern "C" void kernel_launch(void* const* d_in, const int* in_sizes, int n_in,
                              void* d_out, int out_size)
{
    const float* fr = (const float*)d_in[0];
    const float* fq = (const float*)d_in[1];
    float* out = (float*)d_out;

    norm_kernel<<<(BB * HWSZ + 255) / 256, 256>>>(fr, fq);

    dim3 grid(WW / XT, HH / YT, BB);   // (2, 24, 8) = 384 blocks
    corr_kernel<<<grid, NTHR>>>(fr, fq, out);
}